// round 13
// baseline (speedup 1.0000x reference)
#include <cuda_runtime.h>
#include <cuda_fp16.h>
#include <cstdint>

#define CB 32
#define CC 256
#define CH 56
#define CW 56
#define HP 58
#define WP 58
#define WPIX (HP*WP)          // 3364 padded positions per image
#define NPIX (CB*CH*CW)       // 100352 output pixels
#define TILES 26              // 26*128 = 3328 > last valid q (55*58+55 = 3245)
#define KSTAGES 72            // 9 taps * 8 chunks of 32 channels
#define STAGE_STRIDE 24576    // A 8KB + B 16KB per stage
#define BAR_OFF 73728         // 3 stages * 24576

typedef unsigned short ushort_t;

// ---------------- scratch (device globals; no allocation) ----------------
__device__ __align__(128) ushort_t g_xq[(size_t)CB*WPIX*CC + 131072]; // fp16 ±1/0 padded NHWC + tail slack
__device__ __align__(128) ushort_t g_wq[9*CC*CC];                     // fp16 sign weights [tap][o][i]
__device__ float  g_alpha[CC];
__device__ __align__(16) ushort_t g_acc[(size_t)NPIX*CC];             // [b][h][w][o] f16 (exact even ints)
__device__ long long          g_sum[CC];
__device__ unsigned long long g_sumsq[CC];
__device__ float g_scale[CC], g_shift[CC];

#define PONE 0x3C00   // fp16 +1.0
#define NONE 0xBC00   // fp16 -1.0

// ---------------- helpers ----------------
__device__ __forceinline__ void cpa16(uint32_t dst, const void* src) {
    asm volatile("cp.async.cg.shared.global [%0], [%1], 16;\n" :: "r"(dst), "l"(src));
}
__device__ __forceinline__ void ldm4(uint32_t addr, unsigned &r0, unsigned &r1,
                                     unsigned &r2, unsigned &r3) {
    asm volatile("ldmatrix.sync.aligned.m8n8.x4.shared.b16 {%0,%1,%2,%3}, [%4];\n"
        : "=r"(r0), "=r"(r1), "=r"(r2), "=r"(r3) : "r"(addr));
}
// f16-accumulator HMMA: exact for even-integer sums |v| <= 4096
__device__ __forceinline__ void hmma16(unsigned* c, const unsigned* a, unsigned b0, unsigned b1) {
    asm volatile("mma.sync.aligned.m16n8k16.row.col.f16.f16.f16.f16 "
        "{%0,%1}, {%2,%3,%4,%5}, {%6,%7}, {%0,%1};\n"
        : "+r"(c[0]), "+r"(c[1])
        : "r"(a[0]), "r"(a[1]), "r"(a[2]), "r"(a[3]), "r"(b0), "r"(b1));
}
// swizzle for 64B rows: 4 x 16B chunks, chunk' = chunk ^ ((row>>1)&3)
__device__ __forceinline__ uint32_t swz64(int row, int c) {
    return (uint32_t)(row * 64 + ((c ^ ((row >> 1) & 3)) * 16));
}
__device__ __forceinline__ void mbar_init(uint32_t addr, int cnt) {
    asm volatile("mbarrier.init.shared.b64 [%0], %1;" :: "r"(addr), "r"(cnt) : "memory");
}
__device__ __forceinline__ void mbar_arrive(uint32_t addr) {
    asm volatile("mbarrier.arrive.shared.b64 _, [%0];" :: "r"(addr) : "memory");
}
__device__ __forceinline__ void mbar_wait(uint32_t addr, int parity) {
    asm volatile(
        "{\n\t.reg .pred P;\n\t"
        "LAB_%=:\n\t"
        "mbarrier.try_wait.parity.acquire.cta.shared::cta.b64 P, [%0], %1, 0x989680;\n\t"
        "@!P bra LAB_%=;\n\t}"
        :: "r"(addr), "r"(parity) : "memory");
}

// ---------------- 1) zero halo + slack of padded activation buffer ----------------
__global__ void k_zero_halo() {
    int idx = blockIdx.x * blockDim.x + threadIdx.x;
    const int HALO = 228;                       // per image
    const int NHALO = HALO * CB * 32;           // 32 vec16 per position (256 ch)
    if (idx < NHALO) {
        int vec = idx & 31;                     // 8-channel group
        int pid = idx >> 5;
        int img = pid / HALO, r = pid % HALO;
        int q;
        if (r < 58) q = r;                        // top row
        else if (r < 116) q = 57 * WP + (r - 58); // bottom row
        else { int rr = r - 116; q = (1 + (rr >> 1)) * WP + ((rr & 1) * 57); }
        *(int4*)(g_xq + ((size_t)img * WPIX + q) * CC + vec * 8) = make_int4(0, 0, 0, 0);
    } else {
        int j = idx - NHALO;
        if (j < 131072 / 8)
            *(int4*)(g_xq + (size_t)CB * WPIX * CC + j * 8) = make_int4(0, 0, 0, 0);
    }
}

// ---------------- 2) binarize + NCHW -> padded NHWC fp16 ----------------
__global__ void k_pack(const float* __restrict__ x) {
    int bh = blockIdx.x; int b = bh / CH, h = bh % CH;
    int ic = blockIdx.y;                                  // 32-channel chunk
    __shared__ ushort_t tile[32][65];
    int tx = threadIdx.x & 31, ty = threadIdx.x >> 5;     // ty 0..7
    const float* xp = x + (((size_t)(b * CC + ic * 32) * CH) + h) * CW;
    #pragma unroll
    for (int ii = 0; ii < 4; ii++) {
        int il = ty * 4 + ii;
        const float* row = xp + (size_t)il * CH * CW;
        #pragma unroll
        for (int wc2 = 0; wc2 < 2; wc2++) {
            int w = wc2 * 32 + tx;
            if (w < CW) tile[il][w] = (row[w] >= 0.f) ? (ushort_t)PONE : (ushort_t)NONE;
        }
    }
    __syncthreads();
    ushort_t* dst0 = g_xq + ((size_t)(b * HP + h + 1) * WP + 1) * CC + ic * 32 + tx;
    for (int w = ty; w < CW; w += 8)
        dst0[(size_t)w * CC] = tile[tx][w];
}

// ---------------- 3) weight prep (+ stats zero) ----------------
__global__ void k_prep_weights(const float* __restrict__ w) {
    int o = blockIdx.x, t = threadIdx.x;          // t = input channel i
    __shared__ float red[256];
    if (t == 0) { g_sum[o] = 0; g_sumsq[o] = 0; }
    const float* wo = w + (size_t)o * CC * 9;
    float wv[9];
    #pragma unroll
    for (int tap = 0; tap < 9; tap++) wv[tap] = wo[t * 9 + tap];
    float absacc = 0.f;
    #pragma unroll
    for (int tap = 0; tap < 9; tap++) {
        red[t] = wv[tap]; __syncthreads();
        for (int s = 128; s > 0; s >>= 1) { if (t < s) red[t] += red[t + s]; __syncthreads(); }
        float m = red[0] * (1.0f / 256.0f);
        __syncthreads();
        float wc = wv[tap] - m;
        wc = fminf(1.f, fmaxf(-1.f, wc));
        absacc += fabsf(wc);
        g_wq[((size_t)tap * CC + o) * CC + t] = (wc >= 0.f) ? (ushort_t)PONE : (ushort_t)NONE;
    }
    red[t] = absacc; __syncthreads();
    for (int s = 128; s > 0; s >>= 1) { if (t < s) red[t] += red[t + s]; __syncthreads(); }
    if (t == 0) g_alpha[o] = red[0] * (1.0f / 2304.0f);
}

// ---------------- 4) conv: warp-specialized fp16 HMMA implicit GEMM ---------------
// CTA: 288 threads = 8 consumer warps (M=128 x N=256, 64x64 tiles) + 1 producer warp.
// K=2304 (72 stages of 32 channels), 3-stage mbarrier ring, NO __syncthreads in loop.
// smem/CTA: 3 x (A 8KB + B 16KB) + mbarriers. 2 CTAs/SM.
__global__ void __launch_bounds__(288, 2) k_conv() {
    extern __shared__ __align__(128) char sm[];
    uint32_t sbase = (uint32_t)__cvta_generic_to_shared(sm);
    uint32_t bar = sbase + BAR_OFF;            // full[0..2] at +0,8,16; empty[0..2] at +24,32,40
    int tid = threadIdx.x;
    int warp = tid >> 5, lane = tid & 31;
    int img = blockIdx.x / TILES, tile = blockIdx.x % TILES;
    int q0 = tile * 128;

    if (tid == 0) {
        #pragma unroll
        for (int i = 0; i < 3; i++) {
            mbar_init(bar + i * 8, 1);         // full: producer lane0
            mbar_init(bar + 24 + i * 8, 8);    // empty: 8 consumer warps
        }
    }
    __syncthreads();

    unsigned acc[4][8][2];                     // f16x2 accumulators (exact)
    #pragma unroll
    for (int i = 0; i < 4; i++)
        #pragma unroll
        for (int j = 0; j < 8; j++)
            acc[i][j][0] = acc[i][j][1] = 0u;

    if (warp == 8) {
        // ---------------- producer warp ----------------
        int x = (lane >> 1) & 3;
        uint32_t co[4];
        #pragma unroll
        for (int c = 0; c < 4; c++) co[c] = (uint32_t)(((c ^ x) * 16));
        uint32_t dA = sbase + lane * 64;
        uint32_t dB = sbase + 8192 + lane * 64;
        const ushort_t* pA = g_xq + ((size_t)img * WPIX + q0 + lane) * CC;
        const ushort_t* pB = g_wq + (size_t)lane * CC;
        int pe_b = 0, pe_ph = 0, fb = 0;
        #pragma unroll 1
        for (int s = 0; s < KSTAGES; s++) {
            int tap = s >> 3, kc = s & 7;
            int dh = tap / 3, dw = tap - dh * 3;
            if (s >= 3) {
                mbar_wait(bar + 24 + pe_b * 8, pe_ph);
                if (++pe_b == 3) { pe_b = 0; pe_ph ^= 1; }
            }
            int buf = s - (s / 3) * 3;
            const ushort_t* a = pA + (dh * WP + dw) * CC + kc * 32;
            const ushort_t* b = pB + (size_t)tap * CC * CC + kc * 32;
            uint32_t ab = dA + buf * STAGE_STRIDE;
            uint32_t bb = dB + buf * STAGE_STRIDE;
            #pragma unroll
            for (int r = 0; r < 4; r++)
                #pragma unroll
                for (int c = 0; c < 4; c++)
                    cpa16(ab + r * 2048 + co[c], a + r * 32 * CC + c * 8);
            #pragma unroll
            for (int r = 0; r < 8; r++)
                #pragma unroll
                for (int c = 0; c < 4; c++)
                    cpa16(bb + r * 2048 + co[c], b + r * 32 * CC + c * 8);
            asm volatile("cp.async.commit_group;" ::: "memory");
            if (s >= 2) {
                asm volatile("cp.async.wait_group 2;" ::: "memory");
                __syncwarp();
                if (lane == 0) mbar_arrive(bar + fb * 8);
                if (++fb == 3) fb = 0;
            }
        }
        asm volatile("cp.async.wait_group 1;" ::: "memory");
        __syncwarp();
        if (lane == 0) mbar_arrive(bar + fb * 8);
        if (++fb == 3) fb = 0;
        asm volatile("cp.async.wait_group 0;" ::: "memory");
        __syncwarp();
        if (lane == 0) mbar_arrive(bar + fb * 8);
    } else {
        // ---------------- consumer warps 0..7 ----------------
        int wm = warp & 1, wn = warp >> 1;             // 2(M) x 4(N), 64x64 tiles
        int t8 = lane >> 3, r8 = lane & 7;
        int rowA = wm * 64 + (t8 & 1) * 8 + r8;
        int rowB = wn * 64 + (t8 & 1) * 8 + r8;
        int chalf = t8 >> 1;
        uint32_t a0[2], b0[2];
        #pragma unroll
        for (int kk = 0; kk < 2; kk++) {
            a0[kk] = swz64(rowA, kk * 2 + chalf);
            b0[kk] = 8192 + swz64(rowB, kk * 2 + chalf);
        }
        int cb = 0, cph = 0;
        #pragma unroll 1
        for (int s = 0; s < KSTAGES; s++) {
            mbar_wait(bar + cb * 8, cph);
            uint32_t base = sbase + cb * STAGE_STRIDE;
            unsigned af[4][4], bf[4][4];
            // kk = 0
            #pragma unroll
            for (int mt = 0; mt < 4; mt++)
                ldm4(base + a0[0] + mt * 1024, af[mt][0], af[mt][1], af[mt][2], af[mt][3]);
            #pragma unroll
            for (int nb = 0; nb < 4; nb++)
                ldm4(base + b0[0] + nb * 1024, bf[nb][0], bf[nb][1], bf[nb][2], bf[nb][3]);
            #pragma unroll
            for (int mt = 0; mt < 4; mt++)
                #pragma unroll
                for (int nb = 0; nb < 4; nb++) {
                    hmma16(acc[mt][2 * nb],     af[mt], bf[nb][0], bf[nb][2]);
                    hmma16(acc[mt][2 * nb + 1], af[mt], bf[nb][1], bf[nb][3]);
                }
            // kk = 1 fragment loads, then release the buffer early
            #pragma unroll
            for (int mt = 0; mt < 4; mt++)
                ldm4(base + a0[1] + mt * 1024, af[mt][0], af[mt][1], af[mt][2], af[mt][3]);
            #pragma unroll
            for (int nb = 0; nb < 4; nb++)
                ldm4(base + b0[1] + nb * 1024, bf[nb][0], bf[nb][1], bf[nb][2], bf[nb][3]);
            __syncwarp();
            if (lane == 0) mbar_arrive(bar + 24 + cb * 8);
            #pragma unroll
            for (int mt = 0; mt < 4; mt++)
                #pragma unroll
                for (int nb = 0; nb < 4; nb++) {
                    hmma16(acc[mt][2 * nb],     af[mt], bf[nb][0], bf[nb][2]);
                    hmma16(acc[mt][2 * nb + 1], af[mt], bf[nb][1], bf[nb][3]);
                }
            if (++cb == 3) { cb = 0; cph ^= 1; }
        }
    }

    // ---------------- epilogue: store packed f16 + fused per-channel stats -----------
    __syncthreads();
    int* red_s = (int*)sm;            // [2][256] overlay on stage smem (long consumed)
    int* red_q = (int*)sm + 512;      // [2][256]

    if (warp < 8) {
        int wm = warp & 1, wn = warp >> 1;
        int g = lane >> 2, t4 = lane & 3;
        ushort_t* p1[4]; ushort_t* p2[4]; bool v1[4], v2[4];
        #pragma unroll
        for (int mt = 0; mt < 4; mt++) {
            int m = wm * 64 + mt * 16 + g;
            int q = q0 + m;
            int hh = q / WP, ww = q - hh * WP;
            v1[mt] = (hh < CH) && (ww < CW);
            p1[mt] = g_acc + ((size_t)((img * CH + (v1[mt] ? hh : 0)) * CW + (v1[mt] ? ww : 0))) * CC;
            int q2 = q + 8;
            int hh2 = q2 / WP, ww2 = q2 - hh2 * WP;
            v2[mt] = (hh2 < CH) && (ww2 < CW);
            p2[mt] = g_acc + ((size_t)((img * CH + (v2[mt] ? hh2 : 0)) * CW + (v2[mt] ? ww2 : 0))) * CC;
        }
        #pragma unroll
        for (int nt = 0; nt < 8; nt++) {
            int n = wn * 64 + nt * 8 + t4 * 2;
            int s0 = 0, s1 = 0; unsigned u0 = 0, u1 = 0;
            #pragma unroll
            for (int mt = 0; mt < 4; mt++) {
                if (v1[mt]) {
                    *(uint32_t*)(p1[mt] + n) = acc[mt][nt][0];
                    float2 f01 = __half22float2(*(const __half2*)&acc[mt][nt][0]);
                    int i0 = (int)f01.x, i1 = (int)f01.y;
                    s0 += i0; u0 += (unsigned)(i0 * i0);
                    s1 += i1; u1 += (unsigned)(i1 * i1);
                }
                if (v2[mt]) {
                    *(uint32_t*)(p2[mt] + n) = acc[mt][nt][1];
                    float2 f23 = __half22float2(*(const __half2*)&acc[mt][nt][1]);
                    int i2 = (int)f23.x, i3 = (int)f23.y;
                    s0 += i2; u0 += (unsigned)(i2 * i2);
                    s1 += i3; u1 += (unsigned)(i3 * i3);
                }
            }
            #pragma unroll
            for (int off = 4; off < 32; off <<= 1) {
                s0 += __shfl_xor_sync(0xffffffffu, s0, off);
                s1 += __shfl_xor_sync(0xffffffffu, s1, off);
                u0 += __shfl_xor_sync(0xffffffffu, u0, off);
                u1 += __shfl_xor_sync(0xffffffffu, u1, off);
            }
            if (g == 0) {
                red_s[wm * 256 + n] = s0;      red_s[wm * 256 + n + 1] = s1;
                red_q[wm * 256 + n] = (int)u0; red_q[wm * 256 + n + 1] = (int)u1;
            }
        }
    }
    __syncthreads();
    if (tid < 256) {
        long long ts = (long long)red_s[tid] + (long long)red_s[256 + tid];
        long long tq = (long long)(unsigned)red_q[tid] + (long long)(unsigned)red_q[256 + tid];
        atomicAdd((unsigned long long*)&g_sum[tid], (unsigned long long)ts);
        atomicAdd(&g_sumsq[tid], (unsigned long long)tq);
    }
}

// ---------------- 5) per-channel scale/shift ----------------
__global__ void k_finalize(const float* __restrict__ gamma, const float* __restrict__ beta) {
    int o = threadIdx.x;
    double N = (double)NPIX;
    double mean = (double)g_sum[o] / N;
    double ex2  = (double)g_sumsq[o] / N;
    double var  = ex2 - mean * mean;
    double a    = (double)g_alpha[o];
    double inv  = 1.0 / sqrt(a * a * var + 1e-5);
    double sc   = (double)gamma[o] * a * inv;
    g_scale[o] = (float)sc;
    g_shift[o] = (float)((double)beta[o] - sc * mean);
}

// ---------------- 6) affine + relu + f16 NHWC -> f32 NCHW ----------------
__global__ void k_epilogue(float* __restrict__ out) {
    __shared__ float tile[64][57];
    int bh = blockIdx.x, oc = blockIdx.y;
    int b = bh / CH, h = bh % CH;
    const ushort_t* accp = g_acc + (size_t)bh * CW * CC + oc * 64;
    int t = threadIdx.x;
    int ol = t & 63, wq = t >> 6;
    float sc = g_scale[oc * 64 + ol], sh = g_shift[oc * 64 + ol];
    for (int w = wq; w < CW; w += 4) {
        float v = __half2float(*(const __half*)&accp[(size_t)w * CC + ol]);
        tile[ol][w] = fmaxf(fmaf(sc, v, sh), 0.f);
    }
    __syncthreads();
    float* op = out + ((size_t)(b * CC + oc * 64) * CH + h) * CW;
    for (int idx = t; idx < 64 * CW; idx += 256) {
        int o_l = idx / CW, w = idx - o_l * CW;
        op[(size_t)o_l * CH * CW + w] = tile[o_l][w];
    }
}

// ---------------- launch ----------------
extern "C" void kernel_launch(void* const* d_in, const int* in_sizes, int n_in,
                              void* d_out, int out_size) {
    (void)in_sizes; (void)n_in; (void)out_size;
    const float* x     = (const float*)d_in[0];
    const float* w     = (const float*)d_in[1];
    // d_in[2] = bias: cancels exactly under training-mode BN
    const float* gamma = (const float*)d_in[3];
    const float* beta  = (const float*)d_in[4];
    float* out = (float*)d_out;

    cudaFuncSetAttribute(k_conv, cudaFuncAttributeMaxDynamicSharedMemorySize, 73792);

    int zthreads = 228 * CB * 32 + 131072 / 8;
    k_zero_halo<<<(zthreads + 255) / 256, 256>>>();
    k_pack<<<dim3(CB * CH, 8), 256>>>(x);
    k_prep_weights<<<CC, 256>>>(w);
    k_conv<<<CB * TILES, 288, 73792>>>();            // 4th launch -> ncu capture slot
    k_finalize<<<1, 256>>>(gamma, beta);
    k_epilogue<<<dim3(CB * CH, 4), 256>>>(out);
}

// round 15
// speedup vs baseline: 1.3797x; 1.3797x over previous
#include <cuda_runtime.h>
#include <cuda_fp16.h>
#include <cstdint>

#define CB 32
#define CC 256
#define CH 56
#define CW 56
#define HP 58
#define WP 58
#define WPIX (HP*WP)          // 3364 padded positions per image
#define NPIX (CB*CH*CW)       // 100352 output pixels
#define TILES 26              // 26*128 = 3328 > last valid q (55*58+55 = 3245)
#define KSTAGES 36            // 9 taps * 4 chunks of 64 channels (64 fp8 bytes)

typedef unsigned short ushort_t;

// ---------------- scratch (device globals; no allocation) ----------------
__device__ __align__(128) uint8_t g_xq[(size_t)CB*WPIX*CC + 131072]; // e4m3 ±1/0 padded NHWC + tail slack
__device__ __align__(128) uint8_t g_wq[9*CC*CC];                     // e4m3 sign weights [tap][o][i]
__device__ float  g_alpha[CC];
__device__ __align__(16) ushort_t g_acc[(size_t)NPIX*CC];            // [b][h][w][o] f16 (exact even ints)
__device__ long long          g_sum[CC];
__device__ unsigned long long g_sumsq[CC];
__device__ float g_scale[CC], g_shift[CC];

#define PONE8 0x38   // e4m3 +1.0
#define NONE8 0xB8   // e4m3 -1.0

// ---------------- helpers ----------------
__device__ __forceinline__ void cpa16(uint32_t dst, const void* src) {
    asm volatile("cp.async.cg.shared.global [%0], [%1], 16;\n" :: "r"(dst), "l"(src));
}
__device__ __forceinline__ void ldm4(uint32_t addr, unsigned &r0, unsigned &r1,
                                     unsigned &r2, unsigned &r3) {
    asm volatile("ldmatrix.sync.aligned.m8n8.x4.shared.b16 {%0,%1,%2,%3}, [%4];\n"
        : "=r"(r0), "=r"(r1), "=r"(r2), "=r"(r3) : "r"(addr));
}
// FP8 e4m3 MMA, f16 accumulator: exact for even-integer sums |v| <= 4096
__device__ __forceinline__ void qmma(unsigned* c, const unsigned* a, unsigned b0, unsigned b1) {
    asm volatile("mma.sync.aligned.m16n8k32.row.col.f16.e4m3.e4m3.f16 "
        "{%0,%1}, {%2,%3,%4,%5}, {%6,%7}, {%0,%1};\n"
        : "+r"(c[0]), "+r"(c[1])
        : "r"(a[0]), "r"(a[1]), "r"(a[2]), "r"(a[3]), "r"(b0), "r"(b1));
}
// swizzle for 64B rows: 4 x 16B chunks, chunk' = chunk ^ ((row>>1)&3)
__device__ __forceinline__ uint32_t swz64(int row, int c) {
    return (uint32_t)(row * 64 + ((c ^ ((row >> 1) & 3)) * 16));
}

// ---------------- 1) zero halo + slack of padded activation buffer ----------------
__global__ void k_zero_halo() {
    int idx = blockIdx.x * blockDim.x + threadIdx.x;
    const int HALO = 228;                       // per image
    const int NHALO = HALO * CB * 16;           // 16 vec16 per position (256 ch x 1B)
    if (idx < NHALO) {
        int vec = idx & 15;                     // 16-byte group
        int pid = idx >> 4;
        int img = pid / HALO, r = pid % HALO;
        int q;
        if (r < 58) q = r;                        // top row
        else if (r < 116) q = 57 * WP + (r - 58); // bottom row
        else { int rr = r - 116; q = (1 + (rr >> 1)) * WP + ((rr & 1) * 57); }
        *(int4*)(g_xq + ((size_t)img * WPIX + q) * CC + vec * 16) = make_int4(0, 0, 0, 0);
    } else {
        int j = idx - NHALO;
        if (j < 131072 / 16)
            *(int4*)(g_xq + (size_t)CB * WPIX * CC + j * 16) = make_int4(0, 0, 0, 0);
    }
}

// ---------------- 2) binarize + NCHW -> padded NHWC e4m3 ----------------
__global__ void k_pack(const float* __restrict__ x) {
    int bh = blockIdx.x; int b = bh / CH, h = bh % CH;
    int ic = blockIdx.y;                                  // 32-channel chunk
    __shared__ uint8_t tile[32][65];
    int tx = threadIdx.x & 31, ty = threadIdx.x >> 5;     // ty 0..7
    const float* xp = x + (((size_t)(b * CC + ic * 32) * CH) + h) * CW;
    #pragma unroll
    for (int ii = 0; ii < 4; ii++) {
        int il = ty * 4 + ii;
        const float* row = xp + (size_t)il * CH * CW;
        #pragma unroll
        for (int wc2 = 0; wc2 < 2; wc2++) {
            int w = wc2 * 32 + tx;
            if (w < CW) tile[il][w] = (row[w] >= 0.f) ? (uint8_t)PONE8 : (uint8_t)NONE8;
        }
    }
    __syncthreads();
    uint8_t* dst0 = g_xq + ((size_t)(b * HP + h + 1) * WP + 1) * CC + ic * 32 + tx;
    for (int w = ty; w < CW; w += 8)
        dst0[(size_t)w * CC] = tile[tx][w];
}

// ---------------- 3) weight prep (+ stats zero) ----------------
__global__ void k_prep_weights(const float* __restrict__ w) {
    int o = blockIdx.x, t = threadIdx.x;          // t = input channel i
    __shared__ float red[256];
    if (t == 0) { g_sum[o] = 0; g_sumsq[o] = 0; }
    const float* wo = w + (size_t)o * CC * 9;
    float wv[9];
    #pragma unroll
    for (int tap = 0; tap < 9; tap++) wv[tap] = wo[t * 9 + tap];
    float absacc = 0.f;
    #pragma unroll
    for (int tap = 0; tap < 9; tap++) {
        red[t] = wv[tap]; __syncthreads();
        for (int s = 128; s > 0; s >>= 1) { if (t < s) red[t] += red[t + s]; __syncthreads(); }
        float m = red[0] * (1.0f / 256.0f);
        __syncthreads();
        float wc = wv[tap] - m;
        wc = fminf(1.f, fmaxf(-1.f, wc));
        absacc += fabsf(wc);
        g_wq[((size_t)tap * CC + o) * CC + t] = (wc >= 0.f) ? (uint8_t)PONE8 : (uint8_t)NONE8;
    }
    red[t] = absacc; __syncthreads();
    for (int s = 128; s > 0; s >>= 1) { if (t < s) red[t] += red[t + s]; __syncthreads(); }
    if (t == 0) g_alpha[o] = red[0] * (1.0f / 2304.0f);
}

// ---------------- 4) conv: e4m3 QMMA implicit GEMM, f16 acc, 2 CTAs/SM ------------
// CTA: M=128 padded positions x N=256 cout, K=2304 (36 stages of 64 channels,
// depth-3 pipeline, prefetch distance 2). Warp tile 64x64 (2x4 grid), k32 frags.
// smem/CTA: A 3x8KB at [0,24K), B 3x16KB at [24K,72K).
__global__ void __launch_bounds__(256, 2) k_conv() {
    extern __shared__ __align__(128) char sm[];
    uint32_t sbase = (uint32_t)__cvta_generic_to_shared(sm);
    int tid = threadIdx.x;
    int warp = tid >> 5, lane = tid & 31;
    int wm = warp & 1, wn = warp >> 1;                 // 2(M) x 4(N) warp grid, 64x64 tiles
    int img = blockIdx.x / TILES, tile = blockIdx.x % TILES;
    int q0 = tile * 128;

    // cp.async per-thread setup: A row = tid>>1, 2 x 16B chunks; B row = tid, 4 chunks
    int ar = tid >> 1, acb = (tid & 1) * 2;
    const uint8_t* gA = g_xq + ((size_t)img * WPIX + q0 + ar) * CC + acb * 16;
    const uint8_t* gB = g_wq + (size_t)tid * CC;
    uint32_t adst0 = swz64(ar, acb), adst1 = swz64(ar, acb + 1);
    uint32_t bdst[4];
    #pragma unroll
    for (int j = 0; j < 4; j++) bdst[j] = 24576 + swz64(tid, j);

    auto issue = [&](int s) {
        int tap = s >> 2, kc = s & 3;
        int dh = tap / 3, dw = tap - dh * 3;
        int buf = s % 3;
        const uint8_t* a = gA + (dh * WP + dw) * CC + kc * 64;
        uint32_t ab = sbase + buf * 8192;
        cpa16(ab + adst0, a);
        cpa16(ab + adst1, a + 16);
        const uint8_t* b = gB + (size_t)tap * CC * CC + kc * 64;
        uint32_t bb = sbase + buf * 16384;
        #pragma unroll
        for (int j = 0; j < 4; j++) cpa16(bb + bdst[j], b + j * 16);
        asm volatile("cp.async.commit_group;" ::: "memory");
    };

    // ldmatrix per-thread bases (64B-row k32 mapping, R4-proven for 8-bit)
    int t8 = lane >> 3, r8 = lane & 7;
    int rowA = wm * 64 + (t8 & 1) * 8 + r8;
    int rowB = wn * 64 + (t8 & 1) * 8 + r8;
    int chalf = t8 >> 1;
    uint32_t a0[2], b0[2];
    #pragma unroll
    for (int kk = 0; kk < 2; kk++) {
        a0[kk] = swz64(rowA, kk * 2 + chalf);
        b0[kk] = 24576 + swz64(rowB, kk * 2 + chalf);
    }

    unsigned acc[4][8][2];                             // f16x2 accumulators (exact)
    #pragma unroll
    for (int i = 0; i < 4; i++)
        #pragma unroll
        for (int j = 0; j < 8; j++)
            acc[i][j][0] = acc[i][j][1] = 0u;

    issue(0); issue(1);

    #pragma unroll 1
    for (int s = 0; s < KSTAGES; s++) {
        asm volatile("cp.async.wait_group 1;" ::: "memory");
        __syncthreads();
        if (s + 2 < KSTAGES) issue(s + 2);
        else asm volatile("cp.async.commit_group;" ::: "memory");

        int buf = s % 3;
        uint32_t Ab = sbase + buf * 8192;
        uint32_t Bb = sbase + buf * 16384;
        #pragma unroll
        for (int kk = 0; kk < 2; kk++) {
            unsigned af[4][4], bf[4][4];
            #pragma unroll
            for (int mt = 0; mt < 4; mt++)
                ldm4(Ab + a0[kk] + mt * 1024, af[mt][0], af[mt][1], af[mt][2], af[mt][3]);
            #pragma unroll
            for (int nb = 0; nb < 4; nb++)
                ldm4(Bb + b0[kk] + nb * 1024, bf[nb][0], bf[nb][1], bf[nb][2], bf[nb][3]);
            #pragma unroll
            for (int mt = 0; mt < 4; mt++)
                #pragma unroll
                for (int nb = 0; nb < 4; nb++) {
                    qmma(acc[mt][2 * nb],     af[mt], bf[nb][0], bf[nb][2]);
                    qmma(acc[mt][2 * nb + 1], af[mt], bf[nb][1], bf[nb][3]);
                }
        }
    }

    // ---------------- epilogue: store packed f16 + fused per-channel stats -----------
    int g = lane >> 2, t4 = lane & 3;
    ushort_t* p1[4]; ushort_t* p2[4]; bool v1[4], v2[4];
    #pragma unroll
    for (int mt = 0; mt < 4; mt++) {
        int m = wm * 64 + mt * 16 + g;
        int q = q0 + m;
        int hh = q / WP, ww = q - hh * WP;
        v1[mt] = (hh < CH) && (ww < CW);
        p1[mt] = g_acc + ((size_t)((img * CH + (v1[mt] ? hh : 0)) * CW + (v1[mt] ? ww : 0))) * CC;
        int q2 = q + 8;
        int hh2 = q2 / WP, ww2 = q2 - hh2 * WP;
        v2[mt] = (hh2 < CH) && (ww2 < CW);
        p2[mt] = g_acc + ((size_t)((img * CH + (v2[mt] ? hh2 : 0)) * CW + (v2[mt] ? ww2 : 0))) * CC;
    }

    int* red_s = (int*)sm;            // [2][256] overlay on stage smem
    int* red_q = (int*)sm + 512;      // [2][256]

    #pragma unroll
    for (int nt = 0; nt < 8; nt++) {
        int n = wn * 64 + nt * 8 + t4 * 2;
        int s0 = 0, s1 = 0; unsigned u0 = 0, u1 = 0;
        #pragma unroll
        for (int mt = 0; mt < 4; mt++) {
            if (v1[mt]) {
                *(uint32_t*)(p1[mt] + n) = acc[mt][nt][0];
                float2 f01 = __half22float2(*(const __half2*)&acc[mt][nt][0]);
                int i0 = (int)f01.x, i1 = (int)f01.y;
                s0 += i0; u0 += (unsigned)(i0 * i0);
                s1 += i1; u1 += (unsigned)(i1 * i1);
            }
            if (v2[mt]) {
                *(uint32_t*)(p2[mt] + n) = acc[mt][nt][1];
                float2 f23 = __half22float2(*(const __half2*)&acc[mt][nt][1]);
                int i2 = (int)f23.x, i3 = (int)f23.y;
                s0 += i2; u0 += (unsigned)(i2 * i2);
                s1 += i3; u1 += (unsigned)(i3 * i3);
            }
        }
        #pragma unroll
        for (int off = 4; off < 32; off <<= 1) {
            s0 += __shfl_xor_sync(0xffffffffu, s0, off);
            s1 += __shfl_xor_sync(0xffffffffu, s1, off);
            u0 += __shfl_xor_sync(0xffffffffu, u0, off);
            u1 += __shfl_xor_sync(0xffffffffu, u1, off);
        }
        if (g == 0) {
            red_s[wm * 256 + n] = s0;      red_s[wm * 256 + n + 1] = s1;
            red_q[wm * 256 + n] = (int)u0; red_q[wm * 256 + n + 1] = (int)u1;
        }
    }
    __syncthreads();
    if (tid < 256) {
        long long ts = (long long)red_s[tid] + (long long)red_s[256 + tid];
        long long tq = (long long)(unsigned)red_q[tid] + (long long)(unsigned)red_q[256 + tid];
        atomicAdd((unsigned long long*)&g_sum[tid], (unsigned long long)ts);
        atomicAdd(&g_sumsq[tid], (unsigned long long)tq);
    }
}

// ---------------- 5) per-channel scale/shift ----------------
__global__ void k_finalize(const float* __restrict__ gamma, const float* __restrict__ beta) {
    int o = threadIdx.x;
    double N = (double)NPIX;
    double mean = (double)g_sum[o] / N;
    double ex2  = (double)g_sumsq[o] / N;
    double var  = ex2 - mean * mean;
    double a    = (double)g_alpha[o];
    double inv  = 1.0 / sqrt(a * a * var + 1e-5);
    double sc   = (double)gamma[o] * a * inv;
    g_scale[o] = (float)sc;
    g_shift[o] = (float)((double)beta[o] - sc * mean);
}

// ---------------- 6) affine + relu + f16 NHWC -> f32 NCHW ----------------
__global__ void k_epilogue(float* __restrict__ out) {
    __shared__ float tile[64][57];
    int bh = blockIdx.x, oc = blockIdx.y;
    int b = bh / CH, h = bh % CH;
    const ushort_t* accp = g_acc + (size_t)bh * CW * CC + oc * 64;
    int t = threadIdx.x;
    int ol = t & 63, wq = t >> 6;
    float sc = g_scale[oc * 64 + ol], sh = g_shift[oc * 64 + ol];
    for (int w = wq; w < CW; w += 4) {
        float v = __half2float(*(const __half*)&accp[(size_t)w * CC + ol]);
        tile[ol][w] = fmaxf(fmaf(sc, v, sh), 0.f);
    }
    __syncthreads();
    float* op = out + ((size_t)(b * CC + oc * 64) * CH + h) * CW;
    for (int idx = t; idx < 64 * CW; idx += 256) {
        int o_l = idx / CW, w = idx - o_l * CW;
        op[(size_t)o_l * CH * CW + w] = tile[o_l][w];
    }
}

// ---------------- launch ----------------
extern "C" void kernel_launch(void* const* d_in, const int* in_sizes, int n_in,
                              void* d_out, int out_size) {
    (void)in_sizes; (void)n_in; (void)out_size;
    const float* x     = (const float*)d_in[0];
    const float* w     = (const float*)d_in[1];
    // d_in[2] = bias: cancels exactly under training-mode BN
    const float* gamma = (const float*)d_in[3];
    const float* beta  = (const float*)d_in[4];
    float* out = (float*)d_out;

    cudaFuncSetAttribute(k_conv, cudaFuncAttributeMaxDynamicSharedMemorySize, 73728);

    int zthreads = 228 * CB * 16 + 131072 / 16;
    k_zero_halo<<<(zthreads + 255) / 256, 256>>>();
    k_pack<<<dim3(CB * CH, 8), 256>>>(x);
    k_prep_weights<<<CC, 256>>>(w);
    k_conv<<<CB * TILES, 256, 73728>>>();            // 4th launch -> ncu capture slot
    k_finalize<<<1, 256>>>(gamma, beta);
    k_epilogue<<<dim3(CB * CH, 4), 256>>>(out);
}